// round 2
// baseline (speedup 1.0000x reference)
#include <cuda_runtime.h>
#include <math.h>

#define BB 2
#define TT 2048
#define CC 1024
#define HH 16
#define DD 64
#define NTOK (BB*TT)   // 4096

// Scratch (allocation-free contract: __device__ globals)
__device__ float g_q[BB*HH*TT*DD];     // [B,H,T,D]
__device__ float g_k[BB*HH*TT*DD];
__device__ float g_v[BB*HH*TT*DD];
__device__ float g_attn[BB*TT*CC];     // [B,T,C] attention output pre-projection

// ---------------------------------------------------------------------------
// Tiled SGEMM: y = A @ W^T, A [M,K] row-major, W [N,K] row-major (K-major both)
// BM=128, BN=128, BK=16, 256 threads, 8x8 microtile per thread.
// MODE 0: plain [M,N] output. MODE 1: scatter to [B,H,T,D] layout.
// ---------------------------------------------------------------------------
template<int MODE>
__device__ __forceinline__ void gemm_tile_body(
    const float* __restrict__ A, const float* __restrict__ W,
    float* __restrict__ out, int K)
{
    __shared__ float As[16][128];
    __shared__ float Bs[16][128];

    const int tid = threadIdx.x;
    const int m0 = blockIdx.y * 128;
    const int n0 = blockIdx.x * 128;

    const int lr = tid >> 2;          // 0..63
    const int lc = (tid & 3) * 4;     // 0,4,8,12

    const int tx = tid & 15;          // n sub-tile
    const int ty = tid >> 4;          // m sub-tile

    float acc[8][8];
#pragma unroll
    for (int i = 0; i < 8; i++)
#pragma unroll
        for (int j = 0; j < 8; j++) acc[i][j] = 0.f;

    for (int k0 = 0; k0 < K; k0 += 16) {
#pragma unroll
        for (int rr = 0; rr < 2; rr++) {
            int r = lr + rr * 64;
            float4 va = *(const float4*)(A + (size_t)(m0 + r) * K + k0 + lc);
            As[lc + 0][r] = va.x; As[lc + 1][r] = va.y;
            As[lc + 2][r] = va.z; As[lc + 3][r] = va.w;
            float4 vb = *(const float4*)(W + (size_t)(n0 + r) * K + k0 + lc);
            Bs[lc + 0][r] = vb.x; Bs[lc + 1][r] = vb.y;
            Bs[lc + 2][r] = vb.z; Bs[lc + 3][r] = vb.w;
        }
        __syncthreads();

#pragma unroll
        for (int kk = 0; kk < 16; kk++) {
            float a[8], b[8];
            float4 a0 = *(const float4*)&As[kk][ty * 8];
            float4 a1 = *(const float4*)&As[kk][ty * 8 + 4];
            a[0]=a0.x; a[1]=a0.y; a[2]=a0.z; a[3]=a0.w;
            a[4]=a1.x; a[5]=a1.y; a[6]=a1.z; a[7]=a1.w;
            float4 b0 = *(const float4*)&Bs[kk][tx * 8];
            float4 b1 = *(const float4*)&Bs[kk][tx * 8 + 4];
            b[0]=b0.x; b[1]=b0.y; b[2]=b0.z; b[3]=b0.w;
            b[4]=b1.x; b[5]=b1.y; b[6]=b1.z; b[7]=b1.w;
#pragma unroll
            for (int i = 0; i < 8; i++)
#pragma unroll
                for (int j = 0; j < 8; j++)
                    acc[i][j] += a[i] * b[j];
        }
        __syncthreads();
    }

    // Epilogue
#pragma unroll
    for (int i = 0; i < 8; i++) {
        int n = m0 + ty * 8 + i;            // token row
        int o = n0 + tx * 8;                // output column block (8 wide)
        if (MODE == 0) {
            float* dst = out + (size_t)n * CC + o;
            *(float4*)dst       = make_float4(acc[i][0], acc[i][1], acc[i][2], acc[i][3]);
            *(float4*)(dst + 4) = make_float4(acc[i][4], acc[i][5], acc[i][6], acc[i][7]);
        } else {
            int b = n >> 11;                // /T
            int t = n & (TT - 1);
            int h = o >> 6;                 // /D
            int d0 = o & (DD - 1);
            float* dst = out + (((size_t)(b * HH + h) * TT + t) * DD + d0);
            *(float4*)dst       = make_float4(acc[i][0], acc[i][1], acc[i][2], acc[i][3]);
            *(float4*)(dst + 4) = make_float4(acc[i][4], acc[i][5], acc[i][6], acc[i][7]);
        }
    }
}

__global__ __launch_bounds__(256) void qkv_gemm_kernel(
    const float* __restrict__ x,
    const float* __restrict__ wq,
    const float* __restrict__ wk,
    const float* __restrict__ wv)
{
    const float* W = (blockIdx.z == 0) ? wq : (blockIdx.z == 1) ? wk : wv;
    float* out     = (blockIdx.z == 0) ? g_q : (blockIdx.z == 1) ? g_k : g_v;
    gemm_tile_body<1>(x, W, out, CC);
}

__global__ __launch_bounds__(256) void out_gemm_kernel(
    const float* __restrict__ wo, float* __restrict__ out)
{
    gemm_tile_body<0>(g_attn, wo, out, CC);
}

// ---------------------------------------------------------------------------
// Flash attention, causal. One query row per thread (Q, O in registers),
// K/V tiles (64x64) in SMEM with uniform (broadcast) access. 128 threads/CTA.
// grid = (T/128, B*H)
// ---------------------------------------------------------------------------
__global__ __launch_bounds__(128) void attn_kernel()
{
    __shared__ float Ks[64][64];
    __shared__ float Vs[64][64];

    const int bh  = blockIdx.y;
    const int q0  = blockIdx.x * 128;
    const int tid = threadIdx.x;
    const int qrow = q0 + tid;

    const float* qptr = g_q + ((size_t)bh * TT + qrow) * DD;
    float q[64];
#pragma unroll
    for (int d4 = 0; d4 < 16; d4++) {
        float4 v4 = *(const float4*)(qptr + d4 * 4);
        q[d4*4+0] = v4.x; q[d4*4+1] = v4.y; q[d4*4+2] = v4.z; q[d4*4+3] = v4.w;
    }

    float O[64];
#pragma unroll
    for (int d = 0; d < 64; d++) O[d] = 0.f;
    float m = -1e30f, l = 0.f;

    const int smax = q0 + 127;
    const float scale = 0.125f;   // 1/sqrt(64)

    for (int s0 = 0; s0 <= smax; s0 += 64) {
        const float4* kbase = (const float4*)(g_k + ((size_t)bh * TT + s0) * DD);
        const float4* vbase = (const float4*)(g_v + ((size_t)bh * TT + s0) * DD);
        float4* ksm = (float4*)&Ks[0][0];
        float4* vsm = (float4*)&Vs[0][0];
#pragma unroll
        for (int it = 0; it < 8; it++) {
            int idx = tid + it * 128;       // 0..1023 float4s
            ksm[idx] = kbase[idx];
            vsm[idx] = vbase[idx];
        }
        __syncthreads();

        int slim = qrow - s0 + 1;           // # valid keys in this tile for me
        if (slim > 64) slim = 64;

        for (int c0 = 0; c0 < 64; c0 += 16) {
            if (c0 >= slim) break;
            float sc[16];
            float tilemax = -1e30f;
#pragma unroll
            for (int j = 0; j < 16; j++) {
                int s = c0 + j;
                float dot = 0.f;
#pragma unroll
                for (int d = 0; d < 64; d += 4) {
                    float4 kv = *(const float4*)&Ks[s][d];
                    dot += q[d]   * kv.x + q[d+1] * kv.y
                         + q[d+2] * kv.z + q[d+3] * kv.w;
                }
                sc[j] = (s < slim) ? dot * scale : -1e30f;
                tilemax = fmaxf(tilemax, sc[j]);
            }
            float newm = fmaxf(m, tilemax);
            float corr = __expf(m - newm);
            l *= corr;
#pragma unroll
            for (int d = 0; d < 64; d++) O[d] *= corr;
#pragma unroll
            for (int j = 0; j < 16; j++) {
                float p = __expf(sc[j] - newm);
                l += p;
                int s = c0 + j;
#pragma unroll
                for (int d = 0; d < 64; d += 4) {
                    float4 vv = *(const float4*)&Vs[s][d];
                    O[d]   += p * vv.x; O[d+1] += p * vv.y;
                    O[d+2] += p * vv.z; O[d+3] += p * vv.w;
                }
            }
            m = newm;
        }
        __syncthreads();
    }

    const float inv = 1.0f / l;
    const int b = bh / HH, h = bh % HH;
    float* optr = g_attn + ((size_t)(b * TT + qrow)) * CC + h * DD;
#pragma unroll
    for (int d = 0; d < 64; d += 4) {
        *(float4*)(optr + d) = make_float4(O[d]*inv, O[d+1]*inv, O[d+2]*inv, O[d+3]*inv);
    }
}

// ---------------------------------------------------------------------------
extern "C" void kernel_launch(void* const* d_in, const int* in_sizes, int n_in,
                              void* d_out, int out_size)
{
    const float* x  = (const float*)d_in[0];
    const float* wq = (const float*)d_in[1];
    const float* wk = (const float*)d_in[2];
    const float* wv = (const float*)d_in[3];
    const float* wo = (const float*)d_in[4];
    float* out = (float*)d_out;

    dim3 gqkv(CC / 128, NTOK / 128, 3);      // (8, 32, 3)
    qkv_gemm_kernel<<<gqkv, 256>>>(x, wq, wk, wv);

    dim3 gattn(TT / 128, BB * HH);           // (16, 32)
    attn_kernel<<<gattn, 128>>>();

    dim3 gout(CC / 128, NTOK / 128);         // (8, 32)
    out_gemm_kernel<<<gout, 256>>>(wo, out);
}

// round 3
// speedup vs baseline: 1.3496x; 1.3496x over previous
#include <cuda_runtime.h>
#include <cstdint>
#include <math.h>

#define BB 2
#define TT 2048
#define CC 1024
#define HH 16
#define DD 64
#define NTOK (BB*TT)   // 4096

// Scratch (allocation-free contract: __device__ globals)
__device__ float g_q[BB*HH*TT*DD];     // [B,H,T,D]
__device__ float g_k[BB*HH*TT*DD];
__device__ float g_v[BB*HH*TT*DD];
__device__ float g_attn[BB*TT*CC];     // [B,T,C] attention output pre-projection

__device__ __forceinline__ uint32_t f2tf32(float f) {
    uint32_t u;
    asm("cvt.rna.tf32.f32 %0, %1;" : "=r"(u) : "f"(f));
    return u;
}

#define MMA_TF32(d, a, b)                                                      \
    asm volatile(                                                              \
        "mma.sync.aligned.m16n8k8.row.col.f32.tf32.tf32.f32 "                  \
        "{%0,%1,%2,%3}, {%4,%5,%6,%7}, {%8,%9}, {%0,%1,%2,%3};"                \
        : "+f"((d)[0]), "+f"((d)[1]), "+f"((d)[2]), "+f"((d)[3])               \
        : "r"((a)[0]), "r"((a)[1]), "r"((a)[2]), "r"((a)[3]),                  \
          "r"((b)[0]), "r"((b)[1]))

// ---------------------------------------------------------------------------
// tf32 tensor-core GEMM: y = A @ W^T, A [M,K] row-major, W [N,K] row-major.
// BM=128, BN=128, BK=16, 256 threads = 8 warps, warp tile 32(M) x 64(N).
// MODE 0: plain [M,N] output. MODE 1: scatter to [B,H,T,D].
// ---------------------------------------------------------------------------
template<int MODE>
__device__ __forceinline__ void gemm_tf32_body(
    const float* __restrict__ A, const float* __restrict__ W,
    float* __restrict__ out, int K)
{
    // [k][m] / [k][n] layouts; pad 136 so fragment LDS (col*8+row) is
    // conflict-free across all 32 banks (136 mod 32 == 8).
    __shared__ uint32_t As[16][136];
    __shared__ uint32_t Bs[16][136];

    const int tid  = threadIdx.x;
    const int wid  = tid >> 5;
    const int lane = tid & 31;
    const int m0 = blockIdx.y * 128;
    const int n0 = blockIdx.x * 128;

    const int wm = (wid & 3) * 32;    // warp M offset in tile
    const int wn = (wid >> 2) * 64;   // warp N offset in tile

    const int frow = lane >> 2;       // 0..7
    const int fcol = lane & 3;        // 0..3

    float c[2][8][4];
#pragma unroll
    for (int i = 0; i < 2; i++)
#pragma unroll
        for (int j = 0; j < 8; j++)
#pragma unroll
            for (int r = 0; r < 4; r++) c[i][j][r] = 0.f;

    const int lr = tid >> 2;          // 0..63 (row within half-tile)
    const int lc = (tid & 3) * 4;     // 0,4,8,12 (k offset)

    for (int k0 = 0; k0 < K; k0 += 16) {
        // Load + transpose + cvt to tf32
#pragma unroll
        for (int rr = 0; rr < 2; rr++) {
            int r = lr + rr * 64;
            float4 va = *(const float4*)(A + (size_t)(m0 + r) * K + k0 + lc);
            As[lc + 0][r] = f2tf32(va.x); As[lc + 1][r] = f2tf32(va.y);
            As[lc + 2][r] = f2tf32(va.z); As[lc + 3][r] = f2tf32(va.w);
            float4 vb = *(const float4*)(W + (size_t)(n0 + r) * K + k0 + lc);
            Bs[lc + 0][r] = f2tf32(vb.x); Bs[lc + 1][r] = f2tf32(vb.y);
            Bs[lc + 2][r] = f2tf32(vb.z); Bs[lc + 3][r] = f2tf32(vb.w);
        }
        __syncthreads();

#pragma unroll
        for (int ks = 0; ks < 2; ks++) {
            const int kb = ks * 8;
            uint32_t a[2][4], b[8][2];
#pragma unroll
            for (int i = 0; i < 2; i++) {
                int mrow = wm + i * 16 + frow;
                a[i][0] = As[kb + fcol    ][mrow    ];
                a[i][1] = As[kb + fcol    ][mrow + 8];
                a[i][2] = As[kb + fcol + 4][mrow    ];
                a[i][3] = As[kb + fcol + 4][mrow + 8];
            }
#pragma unroll
            for (int j = 0; j < 8; j++) {
                int ncol = wn + j * 8 + frow;
                b[j][0] = Bs[kb + fcol    ][ncol];
                b[j][1] = Bs[kb + fcol + 4][ncol];
            }
#pragma unroll
            for (int i = 0; i < 2; i++)
#pragma unroll
                for (int j = 0; j < 8; j++)
                    MMA_TF32(c[i][j], a[i], b[j]);
        }
        __syncthreads();
    }

    // Epilogue
#pragma unroll
    for (int i = 0; i < 2; i++) {
#pragma unroll
        for (int j = 0; j < 8; j++) {
            int row = m0 + wm + i * 16 + frow;       // token index (row / row+8)
            int col = n0 + wn + j * 8 + 2 * fcol;    // output feature
            if (MODE == 0) {
                float* dst = out + (size_t)row * CC + col;
                *(float2*)dst = make_float2(c[i][j][0], c[i][j][1]);
                float* dst2 = out + (size_t)(row + 8) * CC + col;
                *(float2*)dst2 = make_float2(c[i][j][2], c[i][j][3]);
            } else {
                int h  = col >> 6;
                int d0 = col & (DD - 1);
#pragma unroll
                for (int rh = 0; rh < 2; rh++) {
                    int n = row + rh * 8;
                    int bb = n >> 11;
                    int t  = n & (TT - 1);
                    float* dst = out + (((size_t)(bb * HH + h) * TT + t) * DD + d0);
                    *(float2*)dst = make_float2(c[i][j][rh*2], c[i][j][rh*2+1]);
                }
            }
        }
    }
}

__global__ __launch_bounds__(256) void qkv_gemm_kernel(
    const float* __restrict__ x,
    const float* __restrict__ wq,
    const float* __restrict__ wk,
    const float* __restrict__ wv)
{
    const float* W = (blockIdx.z == 0) ? wq : (blockIdx.z == 1) ? wk : wv;
    float* out     = (blockIdx.z == 0) ? g_q : (blockIdx.z == 1) ? g_k : g_v;
    gemm_tf32_body<1>(x, W, out, CC);
}

__global__ __launch_bounds__(256) void out_gemm_kernel(
    const float* __restrict__ wo, float* __restrict__ out)
{
    gemm_tf32_body<0>(g_attn, wo, out, CC);
}

// ---------------------------------------------------------------------------
// Flash attention, causal. One query row per thread (Q, O in registers),
// K/V tiles (64x64) in SMEM with uniform (broadcast) access. 128 threads/CTA.
// grid = (T/128, B*H)
// ---------------------------------------------------------------------------
__global__ __launch_bounds__(128) void attn_kernel()
{
    __shared__ float Ks[64][64];
    __shared__ float Vs[64][64];

    const int bh  = blockIdx.y;
    const int q0  = blockIdx.x * 128;
    const int tid = threadIdx.x;
    const int qrow = q0 + tid;

    const float* qptr = g_q + ((size_t)bh * TT + qrow) * DD;
    float q[64];
#pragma unroll
    for (int d4 = 0; d4 < 16; d4++) {
        float4 v4 = *(const float4*)(qptr + d4 * 4);
        q[d4*4+0] = v4.x; q[d4*4+1] = v4.y; q[d4*4+2] = v4.z; q[d4*4+3] = v4.w;
    }

    float O[64];
#pragma unroll
    for (int d = 0; d < 64; d++) O[d] = 0.f;
    float m = -1e30f, l = 0.f;

    const int smax = q0 + 127;
    const float scale = 0.125f;   // 1/sqrt(64)

    for (int s0 = 0; s0 <= smax; s0 += 64) {
        const float4* kbase = (const float4*)(g_k + ((size_t)bh * TT + s0) * DD);
        const float4* vbase = (const float4*)(g_v + ((size_t)bh * TT + s0) * DD);
        float4* ksm = (float4*)&Ks[0][0];
        float4* vsm = (float4*)&Vs[0][0];
#pragma unroll
        for (int it = 0; it < 8; it++) {
            int idx = tid + it * 128;       // 0..1023 float4s
            ksm[idx] = kbase[idx];
            vsm[idx] = vbase[idx];
        }
        __syncthreads();

        int slim = qrow - s0 + 1;           // # valid keys in this tile for me
        if (slim > 64) slim = 64;

        for (int c0 = 0; c0 < 64; c0 += 16) {
            if (c0 >= slim) break;
            float sc[16];
            float tilemax = -1e30f;
#pragma unroll
            for (int j = 0; j < 16; j++) {
                int s = c0 + j;
                float dot = 0.f;
#pragma unroll
                for (int d = 0; d < 64; d += 4) {
                    float4 kv = *(const float4*)&Ks[s][d];
                    dot += q[d]   * kv.x + q[d+1] * kv.y
                         + q[d+2] * kv.z + q[d+3] * kv.w;
                }
                sc[j] = (s < slim) ? dot * scale : -1e30f;
                tilemax = fmaxf(tilemax, sc[j]);
            }
            float newm = fmaxf(m, tilemax);
            float corr = __expf(m - newm);
            l *= corr;
#pragma unroll
            for (int d = 0; d < 64; d++) O[d] *= corr;
#pragma unroll
            for (int j = 0; j < 16; j++) {
                float p = __expf(sc[j] - newm);
                l += p;
                int s = c0 + j;
#pragma unroll
                for (int d = 0; d < 64; d += 4) {
                    float4 vv = *(const float4*)&Vs[s][d];
                    O[d]   += p * vv.x; O[d+1] += p * vv.y;
                    O[d+2] += p * vv.z; O[d+3] += p * vv.w;
                }
            }
            m = newm;
        }
        __syncthreads();
    }

    const float inv = 1.0f / l;
    const int b = bh / HH, h = bh % HH;
    float* optr = g_attn + ((size_t)(b * TT + qrow)) * CC + h * DD;
#pragma unroll
    for (int d = 0; d < 64; d += 4) {
        *(float4*)(optr + d) = make_float4(O[d]*inv, O[d+1]*inv, O[d+2]*inv, O[d+3]*inv);
    }
}

// ---------------------------------------------------------------------------
extern "C" void kernel_launch(void* const* d_in, const int* in_sizes, int n_in,
                              void* d_out, int out_size)
{
    const float* x  = (const float*)d_in[0];
    const float* wq = (const float*)d_in[1];
    const float* wk = (const float*)d_in[2];
    const float* wv = (const float*)d_in[3];
    const float* wo = (const float*)d_in[4];
    float* out = (float*)d_out;

    dim3 gqkv(CC / 128, NTOK / 128, 3);      // (8, 32, 3)
    qkv_gemm_kernel<<<gqkv, 256>>>(x, wq, wk, wv);

    dim3 gattn(TT / 128, BB * HH);           // (16, 32)
    attn_kernel<<<gattn, 128>>>();

    dim3 gout(CC / 128, NTOK / 128);         // (8, 32)
    out_gemm_kernel<<<gout, 256>>>(wo, out);
}

// round 5
// speedup vs baseline: 2.9337x; 2.1738x over previous
#include <cuda_runtime.h>
#include <cstdint>
#include <math.h>

#define BB 2
#define TT 2048
#define CC 1024
#define HH 16
#define DD 64
#define NTOK (BB*TT)   // 4096

// Scratch (allocation-free contract: __device__ globals)
__device__ float g_q[BB*HH*TT*DD];     // [B,H,T,D]
__device__ float g_k[BB*HH*TT*DD];
__device__ float g_v[BB*HH*TT*DD];
__device__ float g_attn[BB*TT*CC];     // [B,T,C] attention output pre-projection

__device__ __forceinline__ uint32_t f2tf32(float f) {
    uint32_t u;
    asm("cvt.rna.tf32.f32 %0, %1;" : "=r"(u) : "f"(f));
    return u;
}
__device__ __forceinline__ float ex2(float x) {
    float y;
    asm("ex2.approx.f32 %0, %1;" : "=f"(y) : "f"(x));
    return y;
}

#define MMA_TF32(d, a, b)                                                      \
    asm volatile(                                                              \
        "mma.sync.aligned.m16n8k8.row.col.f32.tf32.tf32.f32 "                  \
        "{%0,%1,%2,%3}, {%4,%5,%6,%7}, {%8,%9}, {%0,%1,%2,%3};"                \
        : "+f"((d)[0]), "+f"((d)[1]), "+f"((d)[2]), "+f"((d)[3])               \
        : "r"((a)[0]), "r"((a)[1]), "r"((a)[2]), "r"((a)[3]),                  \
          "r"((b)[0]), "r"((b)[1]))

// ---------------------------------------------------------------------------
// tf32 tensor-core GEMM: y = A @ W^T  (unchanged from R2)
// ---------------------------------------------------------------------------
template<int MODE>
__device__ __forceinline__ void gemm_tf32_body(
    const float* __restrict__ A, const float* __restrict__ W,
    float* __restrict__ out, int K)
{
    __shared__ uint32_t As[16][136];
    __shared__ uint32_t Bs[16][136];

    const int tid  = threadIdx.x;
    const int wid  = tid >> 5;
    const int lane = tid & 31;
    const int m0 = blockIdx.y * 128;
    const int n0 = blockIdx.x * 128;

    const int wm = (wid & 3) * 32;
    const int wn = (wid >> 2) * 64;
    const int frow = lane >> 2;
    const int fcol = lane & 3;

    float c[2][8][4];
#pragma unroll
    for (int i = 0; i < 2; i++)
#pragma unroll
        for (int j = 0; j < 8; j++)
#pragma unroll
            for (int r = 0; r < 4; r++) c[i][j][r] = 0.f;

    const int lr = tid >> 2;
    const int lc = (tid & 3) * 4;

    for (int k0 = 0; k0 < K; k0 += 16) {
#pragma unroll
        for (int rr = 0; rr < 2; rr++) {
            int r = lr + rr * 64;
            float4 va = *(const float4*)(A + (size_t)(m0 + r) * K + k0 + lc);
            As[lc + 0][r] = f2tf32(va.x); As[lc + 1][r] = f2tf32(va.y);
            As[lc + 2][r] = f2tf32(va.z); As[lc + 3][r] = f2tf32(va.w);
            float4 vb = *(const float4*)(W + (size_t)(n0 + r) * K + k0 + lc);
            Bs[lc + 0][r] = f2tf32(vb.x); Bs[lc + 1][r] = f2tf32(vb.y);
            Bs[lc + 2][r] = f2tf32(vb.z); Bs[lc + 3][r] = f2tf32(vb.w);
        }
        __syncthreads();

#pragma unroll
        for (int ks = 0; ks < 2; ks++) {
            const int kb = ks * 8;
            uint32_t a[2][4], b[8][2];
#pragma unroll
            for (int i = 0; i < 2; i++) {
                int mrow = wm + i * 16 + frow;
                a[i][0] = As[kb + fcol    ][mrow    ];
                a[i][1] = As[kb + fcol    ][mrow + 8];
                a[i][2] = As[kb + fcol + 4][mrow    ];
                a[i][3] = As[kb + fcol + 4][mrow + 8];
            }
#pragma unroll
            for (int j = 0; j < 8; j++) {
                int ncol = wn + j * 8 + frow;
                b[j][0] = Bs[kb + fcol    ][ncol];
                b[j][1] = Bs[kb + fcol + 4][ncol];
            }
#pragma unroll
            for (int i = 0; i < 2; i++)
#pragma unroll
                for (int j = 0; j < 8; j++)
                    MMA_TF32(c[i][j], a[i], b[j]);
        }
        __syncthreads();
    }

#pragma unroll
    for (int i = 0; i < 2; i++) {
#pragma unroll
        for (int j = 0; j < 8; j++) {
            int row = m0 + wm + i * 16 + frow;
            int col = n0 + wn + j * 8 + 2 * fcol;
            if (MODE == 0) {
                float* dst = out + (size_t)row * CC + col;
                *(float2*)dst = make_float2(c[i][j][0], c[i][j][1]);
                float* dst2 = out + (size_t)(row + 8) * CC + col;
                *(float2*)dst2 = make_float2(c[i][j][2], c[i][j][3]);
            } else {
                int h  = col >> 6;
                int d0 = col & (DD - 1);
#pragma unroll
                for (int rh = 0; rh < 2; rh++) {
                    int n = row + rh * 8;
                    int bb = n >> 11;
                    int t  = n & (TT - 1);
                    float* dst = out + (((size_t)(bb * HH + h) * TT + t) * DD + d0);
                    *(float2*)dst = make_float2(c[i][j][rh*2], c[i][j][rh*2+1]);
                }
            }
        }
    }
}

__global__ __launch_bounds__(256) void qkv_gemm_kernel(
    const float* __restrict__ x,
    const float* __restrict__ wq,
    const float* __restrict__ wk,
    const float* __restrict__ wv)
{
    const float* W = (blockIdx.z == 0) ? wq : (blockIdx.z == 1) ? wk : wv;
    float* out     = (blockIdx.z == 0) ? g_q : (blockIdx.z == 1) ? g_k : g_v;
    gemm_tf32_body<1>(x, W, out, CC);
}

__global__ __launch_bounds__(256) void out_gemm_kernel(
    const float* __restrict__ wo, float* __restrict__ out)
{
    gemm_tf32_body<0>(g_attn, wo, out, CC);
}

// ---------------------------------------------------------------------------
// tf32 tensor-core flash attention, causal.
// CTA: 256 threads (8 warps), 128 query rows, key tiles of 64.
// Q held as mma fragments in registers; P roundtrips through SMEM (aliases
// the dead Q staging buffer). grid = (T/128, B*H).
//
// Dynamic SMEM layout (uint32 words):
//   Ps/Qs: [64][136]  (k-major, pad 136 -> fcol*136 mod 32 = fcol*8, conflict-free)
//   Ks:    [64][72]   ([d][s],  pad 72  -> fcol*72  mod 32 = fcol*8, conflict-free)
//   Vs:    [64][72]   ([s][d])
// ---------------------------------------------------------------------------
#define PS_W 136
#define KV_W 72
#define PS_OFF 0
#define KS_OFF (64*PS_W)
#define VS_OFF (KS_OFF + 64*KV_W)
#define ATTN_SMEM_WORDS (VS_OFF + 64*KV_W)
#define ATTN_SMEM_BYTES (ATTN_SMEM_WORDS * 4)

__global__ __launch_bounds__(256) void attn_kernel()
{
    extern __shared__ uint32_t sm[];
    uint32_t* Ps = sm + PS_OFF;     // also Q staging
    uint32_t* Ks = sm + KS_OFF;
    uint32_t* Vs = sm + VS_OFF;

    const int tid  = threadIdx.x;
    const int wid  = tid >> 5;
    const int lane = tid & 31;
    const int frow = lane >> 2;
    const int fcol = lane & 3;
    const int wm   = wid * 16;          // warp's M offset (16 rows each, 8 warps)

    const int bh = blockIdx.y;
    const int q0 = blockIdx.x * 128;

    const float SCL = 0.18033688f;      // (1/sqrt(64)) * log2(e)

    // ---- Stage Q tile [128 rows][64 d] -> Qs[d][m], then load fragments ----
    {
        const int m    = tid >> 1;
        const int half = tid & 1;
        const float* qrow = g_q + ((size_t)bh * TT + q0 + m) * DD + half * 32;
#pragma unroll
        for (int i = 0; i < 8; i++) {
            float4 v4 = *(const float4*)(qrow + i * 4);
            int d0 = half * 32 + i * 4;
            Ps[(d0 + 0) * PS_W + m] = f2tf32(v4.x);
            Ps[(d0 + 1) * PS_W + m] = f2tf32(v4.y);
            Ps[(d0 + 2) * PS_W + m] = f2tf32(v4.z);
            Ps[(d0 + 3) * PS_W + m] = f2tf32(v4.w);
        }
    }
    __syncthreads();

    uint32_t qa[8][4];
#pragma unroll
    for (int ks = 0; ks < 8; ks++) {
        int kb = ks * 8;
        qa[ks][0] = Ps[(kb + fcol    ) * PS_W + wm + frow    ];
        qa[ks][1] = Ps[(kb + fcol    ) * PS_W + wm + frow + 8];
        qa[ks][2] = Ps[(kb + fcol + 4) * PS_W + wm + frow    ];
        qa[ks][3] = Ps[(kb + fcol + 4) * PS_W + wm + frow + 8];
    }
    // No sync needed here: the K/V-load sync below orders Qs reads vs Ps writes.

    float co[8][4];                     // O accumulator [d-tile][frag]
#pragma unroll
    for (int j = 0; j < 8; j++)
#pragma unroll
        for (int r = 0; r < 4; r++) co[j][r] = 0.f;
    float mst[2] = {-1e30f, -1e30f};
    float lst[2] = {0.f, 0.f};
    const int rowg[2] = {q0 + wm + frow, q0 + wm + frow + 8};

    const int ntiles = q0 / 64 + 2;

    for (int ti = 0; ti < ntiles; ti++) {
        const int s0 = ti * 64;
        const bool masked = (s0 >= q0);

        // ---- Load K tile -> Ks[d][s] (transposed), V tile -> Vs[s][d] ----
        {
            const int s  = tid & 63;
            const int dg = tid >> 6;    // 0..3
            const float* krow = g_k + ((size_t)bh * TT + s0 + s) * DD + dg * 16;
#pragma unroll
            for (int i = 0; i < 4; i++) {
                float4 v4 = *(const float4*)(krow + i * 4);
                int d0 = dg * 16 + i * 4;
                Ks[(d0 + 0) * KV_W + s] = f2tf32(v4.x);
                Ks[(d0 + 1) * KV_W + s] = f2tf32(v4.y);
                Ks[(d0 + 2) * KV_W + s] = f2tf32(v4.z);
                Ks[(d0 + 3) * KV_W + s] = f2tf32(v4.w);
            }
            const float4* vbase = (const float4*)(g_v + ((size_t)bh * TT + s0) * DD);
#pragma unroll
            for (int it = 0; it < 4; it++) {
                int idx = tid + it * 256;       // 0..1023 float4s
                float4 v4 = vbase[idx];
                int vs = idx >> 4;
                int vd = (idx & 15) * 4;
                uint4 uv;
                uv.x = f2tf32(v4.x); uv.y = f2tf32(v4.y);
                uv.z = f2tf32(v4.z); uv.w = f2tf32(v4.w);
                *(uint4*)&Vs[vs * KV_W + vd] = uv;
            }
        }
        __syncthreads();

        // ---- S = Q K^T (M=16/warp, N=64, K=64) ----
        float sc[8][4];
#pragma unroll
        for (int j = 0; j < 8; j++)
#pragma unroll
            for (int r = 0; r < 4; r++) sc[j][r] = 0.f;
#pragma unroll
        for (int ks = 0; ks < 8; ks++) {
            int kb = ks * 8;
            uint32_t b[8][2];
#pragma unroll
            for (int j = 0; j < 8; j++) {
                b[j][0] = Ks[(kb + fcol    ) * KV_W + j * 8 + frow];
                b[j][1] = Ks[(kb + fcol + 4) * KV_W + j * 8 + frow];
            }
#pragma unroll
            for (int j = 0; j < 8; j++)
                MMA_TF32(sc[j], qa[ks], b[j]);
        }

        // ---- Online softmax (base-2 domain, scale folded) ----
#pragma unroll
        for (int rh = 0; rh < 2; rh++) {
            float tm = -1e30f;
#pragma unroll
            for (int j = 0; j < 8; j++) {
#pragma unroll
                for (int c2 = 0; c2 < 2; c2++) {
                    float v = sc[j][rh*2 + c2] * SCL;
                    if (masked) {
                        int col = s0 + j * 8 + 2 * fcol + c2;
                        if (col > rowg[rh]) v = -1e30f;
                    }
                    sc[j][rh*2 + c2] = v;
                    tm = fmaxf(tm, v);
                }
            }
            tm = fmaxf(tm, __shfl_xor_sync(0xffffffffu, tm, 1));
            tm = fmaxf(tm, __shfl_xor_sync(0xffffffffu, tm, 2));
            float newm = fmaxf(mst[rh], tm);
            float corr = ex2(mst[rh] - newm);
            mst[rh] = newm;
            float psum = 0.f;
#pragma unroll
            for (int j = 0; j < 8; j++) {
#pragma unroll
                for (int c2 = 0; c2 < 2; c2++) {
                    float p = ex2(sc[j][rh*2 + c2] - newm);
                    psum += p;
                    int sj = j * 8 + 2 * fcol + c2;
                    Ps[sj * PS_W + wm + frow + rh * 8] = f2tf32(p);
                }
            }
            lst[rh] = lst[rh] * corr + psum;
#pragma unroll
            for (int j = 0; j < 8; j++) {
                co[j][rh*2 + 0] *= corr;
                co[j][rh*2 + 1] *= corr;
            }
        }
        __syncthreads();   // Ps written by all warps before PV reads

        // ---- O += P V (M=16/warp, N=64(d), K=64(s)) ----
#pragma unroll
        for (int ks = 0; ks < 8; ks++) {
            int kb = ks * 8;
            uint32_t pa[4], b[8][2];
            pa[0] = Ps[(kb + fcol    ) * PS_W + wm + frow    ];
            pa[1] = Ps[(kb + fcol    ) * PS_W + wm + frow + 8];
            pa[2] = Ps[(kb + fcol + 4) * PS_W + wm + frow    ];
            pa[3] = Ps[(kb + fcol + 4) * PS_W + wm + frow + 8];
#pragma unroll
            for (int j = 0; j < 8; j++) {
                b[j][0] = Vs[(kb + fcol    ) * KV_W + j * 8 + frow];
                b[j][1] = Vs[(kb + fcol + 4) * KV_W + j * 8 + frow];
            }
#pragma unroll
            for (int j = 0; j < 8; j++)
                MMA_TF32(co[j], pa, b[j]);
        }
        __syncthreads();   // all reads done before next tile overwrites SMEM
    }

    // ---- Normalize and write out: g_attn[b][t][h*64 + d] ----
    const int b = bh / HH, h = bh % HH;
#pragma unroll
    for (int rh = 0; rh < 2; rh++) {
        float l = lst[rh];
        l += __shfl_xor_sync(0xffffffffu, l, 1);
        l += __shfl_xor_sync(0xffffffffu, l, 2);
        float inv = 1.0f / l;
        int t = rowg[rh];
        float* optr = g_attn + ((size_t)(b * TT + t)) * CC + h * DD;
#pragma unroll
        for (int j = 0; j < 8; j++) {
            int d0 = j * 8 + 2 * fcol;
            *(float2*)(optr + d0) =
                make_float2(co[j][rh*2 + 0] * inv, co[j][rh*2 + 1] * inv);
        }
    }
}

// ---------------------------------------------------------------------------
extern "C" void kernel_launch(void* const* d_in, const int* in_sizes, int n_in,
                              void* d_out, int out_size)
{
    const float* x  = (const float*)d_in[0];
    const float* wq = (const float*)d_in[1];
    const float* wk = (const float*)d_in[2];
    const float* wv = (const float*)d_in[3];
    const float* wo = (const float*)d_in[4];
    float* out = (float*)d_out;

    cudaFuncSetAttribute(attn_kernel,
                         cudaFuncAttributeMaxDynamicSharedMemorySize,
                         ATTN_SMEM_BYTES);

    dim3 gqkv(CC / 128, NTOK / 128, 3);      // (8, 32, 3)
    qkv_gemm_kernel<<<gqkv, 256>>>(x, wq, wk, wv);

    dim3 gattn(TT / 128, BB * HH);           // (16, 32)
    attn_kernel<<<gattn, 256, ATTN_SMEM_BYTES>>>();

    dim3 gout(CC / 128, NTOK / 128);         // (8, 32)
    out_gemm_kernel<<<gout, 256>>>(wo, out);
}

// round 6
// speedup vs baseline: 3.1719x; 1.0812x over previous
#include <cuda_runtime.h>
#include <cstdint>
#include <math.h>

#define BB 2
#define TT 2048
#define CC 1024
#define HH 16
#define DD 64
#define NTOK (BB*TT)   // 4096

// Scratch (allocation-free contract: __device__ globals)
__device__ float g_q[BB*HH*TT*DD];     // [B,H,T,D]
__device__ float g_k[BB*HH*TT*DD];     // [B,H,T,D]
__device__ float g_vT[BB*HH*DD*TT];    // [B,H,D,T]  (transposed V)
__device__ float g_attn[BB*TT*CC];     // [B,T,C]

__device__ __forceinline__ uint32_t f2tf32(float f) {
    uint32_t u;
    asm("cvt.rna.tf32.f32 %0, %1;" : "=r"(u) : "f"(f));
    return u;
}
__device__ __forceinline__ float ex2(float x) {
    float y;
    asm("ex2.approx.f32 %0, %1;" : "=f"(y) : "f"(x));
    return y;
}

#define MMA_TF32(d, a, b)                                                      \
    asm volatile(                                                              \
        "mma.sync.aligned.m16n8k8.row.col.f32.tf32.tf32.f32 "                  \
        "{%0,%1,%2,%3}, {%4,%5,%6,%7}, {%8,%9}, {%0,%1,%2,%3};"                \
        : "+f"((d)[0]), "+f"((d)[1]), "+f"((d)[2]), "+f"((d)[3])               \
        : "r"((a)[0]), "r"((a)[1]), "r"((a)[2]), "r"((a)[3]),                  \
          "r"((b)[0]), "r"((b)[1]))

// k-permutation within each 8-k block: word(k) = (k/8)*8 + (k%4)*2 + ((k%8)>=4)
// -> the mma k-pair (fcol, fcol+4) sits at adjacent words = one LDS.64.

// ---------------------------------------------------------------------------
// tf32 tensor-core GEMM: y = A @ W^T, A [M,K] rm, W [N,K] rm.
// BM=BN=128, BK=16, 256 thr = 8 warps, warp tile 32x64.
// SMEM rows: 16 k-words permuted, stride 24 (conflict-free LDS.64 reads).
// MODE 0: [M,N] out. MODE 1: scatter [B,H,T,D]. MODE 2: scatter [B,H,D,T].
// ---------------------------------------------------------------------------
#define GP 24

template<int MODE>
__device__ __forceinline__ void gemm_tf32_body(
    const float* __restrict__ A, const float* __restrict__ W,
    float* __restrict__ out, int K)
{
    __shared__ uint32_t As[128 * GP];
    __shared__ uint32_t Bs[128 * GP];

    const int tid  = threadIdx.x;
    const int wid  = tid >> 5;
    const int lane = tid & 31;
    const int m0 = blockIdx.y * 128;
    const int n0 = blockIdx.x * 128;

    const int wm = (wid & 3) * 32;
    const int wn = (wid >> 2) * 64;
    const int frow = lane >> 2;
    const int fcol = lane & 3;

    float c[2][8][4];
#pragma unroll
    for (int i = 0; i < 2; i++)
#pragma unroll
        for (int j = 0; j < 8; j++)
#pragma unroll
            for (int r = 0; r < 4; r++) c[i][j][r] = 0.f;

    const int lr = tid >> 2;          // 0..63
    const int lc = (tid & 3) * 4;     // 0,4,8,12
    // permuted word base for k = lc+i: ((lc)/8)*8 + ((lc/4)&1) + i*2
    const int kb8 = ((lc >> 3) << 3) + ((lc >> 2) & 1);

    for (int k0 = 0; k0 < K; k0 += 16) {
#pragma unroll
        for (int rr = 0; rr < 2; rr++) {
            int r = lr + rr * 64;
            float4 va = *(const float4*)(A + (size_t)(m0 + r) * K + k0 + lc);
            uint32_t* da = &As[r * GP + kb8];
            da[0] = f2tf32(va.x); da[2] = f2tf32(va.y);
            da[4] = f2tf32(va.z); da[6] = f2tf32(va.w);
            float4 vb = *(const float4*)(W + (size_t)(n0 + r) * K + k0 + lc);
            uint32_t* db = &Bs[r * GP + kb8];
            db[0] = f2tf32(vb.x); db[2] = f2tf32(vb.y);
            db[4] = f2tf32(vb.z); db[6] = f2tf32(vb.w);
        }
        __syncthreads();

#pragma unroll
        for (int ks = 0; ks < 2; ks++) {
            const int kw = ks * 8 + fcol * 2;
            uint32_t a[2][4], b[8][2];
#pragma unroll
            for (int i = 0; i < 2; i++) {
                int mrow = wm + i * 16 + frow;
                uint2 lo = *(const uint2*)&As[mrow * GP + kw];
                uint2 hi = *(const uint2*)&As[(mrow + 8) * GP + kw];
                a[i][0] = lo.x; a[i][1] = hi.x; a[i][2] = lo.y; a[i][3] = hi.y;
            }
#pragma unroll
            for (int j = 0; j < 8; j++) {
                uint2 t = *(const uint2*)&Bs[(wn + j * 8 + frow) * GP + kw];
                b[j][0] = t.x; b[j][1] = t.y;
            }
#pragma unroll
            for (int i = 0; i < 2; i++)
#pragma unroll
                for (int j = 0; j < 8; j++)
                    MMA_TF32(c[i][j], a[i], b[j]);
        }
        __syncthreads();
    }

#pragma unroll
    for (int i = 0; i < 2; i++) {
#pragma unroll
        for (int j = 0; j < 8; j++) {
            int row = m0 + wm + i * 16 + frow;
            int col = n0 + wn + j * 8 + 2 * fcol;
            if (MODE == 0) {
                float* dst = out + (size_t)row * CC + col;
                *(float2*)dst = make_float2(c[i][j][0], c[i][j][1]);
                float* dst2 = out + (size_t)(row + 8) * CC + col;
                *(float2*)dst2 = make_float2(c[i][j][2], c[i][j][3]);
            } else if (MODE == 1) {
                int h  = col >> 6;
                int d0 = col & (DD - 1);
#pragma unroll
                for (int rh = 0; rh < 2; rh++) {
                    int n = row + rh * 8;
                    int bb = n >> 11;
                    int t  = n & (TT - 1);
                    float* dst = out + (((size_t)(bb * HH + h) * TT + t) * DD + d0);
                    *(float2*)dst = make_float2(c[i][j][rh*2], c[i][j][rh*2+1]);
                }
            } else {
                int h  = col >> 6;
                int d0 = col & (DD - 1);
#pragma unroll
                for (int rh = 0; rh < 2; rh++) {
                    int n = row + rh * 8;
                    int bb = n >> 11;
                    int t  = n & (TT - 1);
                    float* base = out + ((size_t)(bb * HH + h) * DD + d0) * TT + t;
                    base[0]  = c[i][j][rh*2];
                    base[TT] = c[i][j][rh*2+1];
                }
            }
        }
    }
}

__global__ __launch_bounds__(256) void qkv_gemm_kernel(
    const float* __restrict__ x,
    const float* __restrict__ wq,
    const float* __restrict__ wk,
    const float* __restrict__ wv)
{
    if (blockIdx.z == 2) {
        gemm_tf32_body<2>(x, wv, g_vT, CC);
    } else {
        const float* W = (blockIdx.z == 0) ? wq : wk;
        float* o       = (blockIdx.z == 0) ? g_q : g_k;
        gemm_tf32_body<1>(x, W, o, CC);
    }
}

__global__ __launch_bounds__(256) void out_gemm_kernel(
    const float* __restrict__ wo, float* __restrict__ out)
{
    gemm_tf32_body<0>(g_attn, wo, out, CC);
}

// ---------------------------------------------------------------------------
// tf32 tensor-core flash attention, causal.
// 256 threads (8 warps), 128 q rows/CTA, key tiles of 64.
// Q frags direct from gmem; K/V/P in permuted-pair SMEM (stride 72) so all
// mainloop fragment loads are LDS.64, conflict-free. grid = (T/128, B*H).
// ---------------------------------------------------------------------------
#define PS_P 72
#define KV_P 72
#define KS_OFF (128 * PS_P)
#define VS_OFF (KS_OFF + 64 * KV_P)
#define ATTN_SMEM_WORDS (VS_OFF + 64 * KV_P)
#define ATTN_SMEM_BYTES (ATTN_SMEM_WORDS * 4)

__global__ __launch_bounds__(256) void attn_kernel()
{
    extern __shared__ uint32_t sm[];
    uint32_t* Ps = sm;
    uint32_t* Ks = sm + KS_OFF;
    uint32_t* Vs = sm + VS_OFF;

    const int tid  = threadIdx.x;
    const int wid  = tid >> 5;
    const int lane = tid & 31;
    const int frow = lane >> 2;
    const int fcol = lane & 3;
    const int wm   = wid * 16;

    const int bh = blockIdx.y;
    const int q0 = blockIdx.x * 128;

    const float SCL = 0.18033688f;      // (1/sqrt(64)) * log2(e)

    // ---- Q fragments straight from gmem ----
    uint32_t qa[8][4];
    {
        const float* qb = g_q + ((size_t)bh * TT + q0 + wm) * DD;
#pragma unroll
        for (int ks = 0; ks < 8; ks++) {
            int dlo = ks * 8 + fcol;
            qa[ks][0] = f2tf32(qb[frow * DD + dlo]);
            qa[ks][1] = f2tf32(qb[(frow + 8) * DD + dlo]);
            qa[ks][2] = f2tf32(qb[frow * DD + dlo + 4]);
            qa[ks][3] = f2tf32(qb[(frow + 8) * DD + dlo + 4]);
        }
    }

    float co[8][4];
#pragma unroll
    for (int j = 0; j < 8; j++)
#pragma unroll
        for (int r = 0; r < 4; r++) co[j][r] = 0.f;
    float mst[2] = {-1e30f, -1e30f};
    float lst[2] = {0.f, 0.f};
    const int rowg[2] = {q0 + wm + frow, q0 + wm + frow + 8};

    // fill-thread mapping: 16 lanes span the contiguous quad dim (coalesced)
    const int dq  = tid & 15;
    const int sr0 = tid >> 4;
    // permuted word base for quad q, elem r: (q/2)*8 + (q&1) + r*2
    const int qb8 = ((dq >> 1) << 3) + (dq & 1);
    // Ps store word offsets (within 8-word block) for c2=0/1
    const int w0 = (fcol & 1) * 4 + (fcol >> 1);

    const int ntiles = q0 / 64 + 2;

    for (int ti = 0; ti < ntiles; ti++) {
        const int s0 = ti * 64;
        const bool masked = (s0 >= q0);

        // ---- Fill K [s][d_perm] and V [d][s_perm] ----
        {
            const float* kbase = g_k + ((size_t)bh * TT + s0) * DD;
            const float* vtb   = g_vT + (size_t)bh * DD * TT + s0;
#pragma unroll
            for (int it = 0; it < 4; it++) {
                int rrow = sr0 + it * 16;
                float4 kv = *(const float4*)(kbase + (size_t)rrow * DD + dq * 4);
                uint32_t* kd = &Ks[rrow * KV_P + qb8];
                kd[0] = f2tf32(kv.x); kd[2] = f2tf32(kv.y);
                kd[4] = f2tf32(kv.z); kd[6] = f2tf32(kv.w);
                float4 vv = *(const float4*)(vtb + (size_t)rrow * TT + dq * 4);
                uint32_t* vd = &Vs[rrow * KV_P + qb8];
                vd[0] = f2tf32(vv.x); vd[2] = f2tf32(vv.y);
                vd[4] = f2tf32(vv.z); vd[6] = f2tf32(vv.w);
            }
        }
        __syncthreads();

        // ---- S = Q K^T ----
        float sc[8][4];
#pragma unroll
        for (int j = 0; j < 8; j++)
#pragma unroll
            for (int r = 0; r < 4; r++) sc[j][r] = 0.f;
#pragma unroll
        for (int ks = 0; ks < 8; ks++) {
            const int kw = ks * 8 + fcol * 2;
            uint32_t b[8][2];
#pragma unroll
            for (int j = 0; j < 8; j++) {
                uint2 t = *(const uint2*)&Ks[(j * 8 + frow) * KV_P + kw];
                b[j][0] = t.x; b[j][1] = t.y;
            }
#pragma unroll
            for (int j = 0; j < 8; j++)
                MMA_TF32(sc[j], qa[ks], b[j]);
        }

        // ---- Online softmax (base-2, scale folded); P -> Ps[m][s_perm] ----
#pragma unroll
        for (int rh = 0; rh < 2; rh++) {
            float tm = -1e30f;
#pragma unroll
            for (int j = 0; j < 8; j++) {
#pragma unroll
                for (int c2 = 0; c2 < 2; c2++) {
                    float v = sc[j][rh*2 + c2] * SCL;
                    if (masked) {
                        int col = s0 + j * 8 + 2 * fcol + c2;
                        if (col > rowg[rh]) v = -1e30f;
                    }
                    sc[j][rh*2 + c2] = v;
                    tm = fmaxf(tm, v);
                }
            }
            tm = fmaxf(tm, __shfl_xor_sync(0xffffffffu, tm, 1));
            tm = fmaxf(tm, __shfl_xor_sync(0xffffffffu, tm, 2));
            float newm = fmaxf(mst[rh], tm);
            float corr = ex2(mst[rh] - newm);
            mst[rh] = newm;
            float psum = 0.f;
            uint32_t* prow = &Ps[(wm + frow + rh * 8) * PS_P];
#pragma unroll
            for (int j = 0; j < 8; j++) {
#pragma unroll
                for (int c2 = 0; c2 < 2; c2++) {
                    float p = ex2(sc[j][rh*2 + c2] - newm);
                    psum += p;
                    prow[j * 8 + w0 + c2 * 2] = f2tf32(p);
                }
            }
            lst[rh] = lst[rh] * corr + psum;
#pragma unroll
            for (int j = 0; j < 8; j++) {
                co[j][rh*2 + 0] *= corr;
                co[j][rh*2 + 1] *= corr;
            }
        }
        __syncwarp();   // warp reads back only its own Ps rows

        // ---- O += P V ----
#pragma unroll
        for (int ks = 0; ks < 8; ks++) {
            const int kw = ks * 8 + fcol * 2;
            uint2 plo = *(const uint2*)&Ps[(wm + frow) * PS_P + kw];
            uint2 phi = *(const uint2*)&Ps[(wm + frow + 8) * PS_P + kw];
            uint32_t pa[4] = {plo.x, phi.x, plo.y, phi.y};
            uint32_t b[8][2];
#pragma unroll
            for (int j = 0; j < 8; j++) {
                uint2 t = *(const uint2*)&Vs[(j * 8 + frow) * KV_P + kw];
                b[j][0] = t.x; b[j][1] = t.y;
            }
#pragma unroll
            for (int j = 0; j < 8; j++)
                MMA_TF32(co[j], pa, b[j]);
        }
        __syncthreads();   // Ks/Vs reads done before next fill
    }

    // ---- Normalize and write: g_attn[b][t][h*64 + d] ----
    const int b = bh / HH, h = bh % HH;
#pragma unroll
    for (int rh = 0; rh < 2; rh++) {
        float l = lst[rh];
        l += __shfl_xor_sync(0xffffffffu, l, 1);
        l += __shfl_xor_sync(0xffffffffu, l, 2);
        float inv = 1.0f / l;
        int t = rowg[rh];
        float* optr = g_attn + ((size_t)(b * TT + t)) * CC + h * DD;
#pragma unroll
        for (int j = 0; j < 8; j++) {
            int d0 = j * 8 + 2 * fcol;
            *(float2*)(optr + d0) =
                make_float2(co[j][rh*2 + 0] * inv, co[j][rh*2 + 1] * inv);
        }
    }
}

// ---------------------------------------------------------------------------
extern "C" void kernel_launch(void* const* d_in, const int* in_sizes, int n_in,
                              void* d_out, int out_size)
{
    const float* x  = (const float*)d_in[0];
    const float* wq = (const float*)d_in[1];
    const float* wk = (const float*)d_in[2];
    const float* wv = (const float*)d_in[3];
    const float* wo = (const float*)d_in[4];
    float* out = (float*)d_out;

    cudaFuncSetAttribute(attn_kernel,
                         cudaFuncAttributeMaxDynamicSharedMemorySize,
                         ATTN_SMEM_BYTES);

    dim3 gqkv(CC / 128, NTOK / 128, 3);      // (8, 32, 3)
    qkv_gemm_kernel<<<gqkv, 256>>>(x, wq, wk, wv);

    dim3 gattn(TT / 128, BB * HH);           // (16, 32)
    attn_kernel<<<gattn, 256, ATTN_SMEM_BYTES>>>();

    dim3 gout(CC / 128, NTOK / 128);         // (8, 32)
    out_gemm_kernel<<<gout, 256>>>(wo, out);
}